// round 15
// baseline (speedup 1.0000x reference)
#include <cuda_runtime.h>
#include <cuda_fp16.h>
#include <cstdint>

// ---------------------------------------------------------------------------
// Problem constants
// ---------------------------------------------------------------------------
#define HH   4
#define HDm  256
#define Dm   1024
#define Sm   4096
#define Bm   8
#define MTOK (Bm * Sm)   // 32768 tokens

// Gate scratch: fp32, [token][d], stored as (tanh z, i_raw, f_raw, sig o).
// i/f stay RAW: the validated stabilized max-chain consumes them unchanged.
__device__ float4 g_gates[(size_t)MTOK * Dm];
// fp16 copies of x and gate-interleaved W for cp.async streaming.
__device__ __half g_xh[(size_t)MTOK * Dm];            // 64 MB
__device__ __half g_wh[(size_t)HH * Dm * HDm];        // 2 MB: [h][n][k], n=o*4+g

#define L2E 1.4426950408889634f

__device__ __forceinline__ uint32_t smem_to_u32(const void* p) {
    uint32_t a;
    asm("{ .reg .u64 t; cvta.to.shared.u64 t, %1; cvt.u32.u64 %0, t; }" : "=r"(a) : "l"(p));
    return a;
}
__device__ __forceinline__ void cp_async16(uint32_t smem_addr, const void* gptr) {
    asm volatile("cp.async.cg.shared.global [%0], [%1], 16;"
                 :: "r"(smem_addr), "l"(gptr) : "memory");
}
__device__ __forceinline__ float mexp(float x) {
    float r; asm("ex2.approx.f32 %0, %1;" : "=f"(r) : "f"(x * L2E)); return r;
}
__device__ __forceinline__ float mtanh(float x) {
    float r; asm("tanh.approx.f32 %0, %1;" : "=f"(r) : "f"(x)); return r;
}
__device__ __forceinline__ float mrcp(float x) {
    float r; asm("rcp.approx.f32 %0, %1;" : "=f"(r) : "f"(x)); return r;
}
__device__ __forceinline__ float msig(float x) {
    return mrcp(1.0f + mexp(-x));
}

// ---- mbarrier helpers ----
#define MBARRIER_INIT(addr, cnt) \
    asm volatile("mbarrier.init.shared.b64 [%0], %1;" :: "r"((uint32_t)(addr)), "r"((uint32_t)(cnt)) : "memory")
#define MBARRIER_EXPECT_TX(addr, bytes) \
    asm volatile("mbarrier.arrive.expect_tx.shared.b64 _, [%0], %1;" :: "r"((uint32_t)(addr)), "r"((uint32_t)(bytes)) : "memory")
#define MBARRIER_ARRIVE(addr) \
    asm volatile("mbarrier.arrive.shared.b64 _, [%0];" :: "r"((uint32_t)(addr)) : "memory")
#define MBARRIER_WAIT_PARITY(addr, par) do {                                       \
    uint32_t _m = (uint32_t)(addr); uint32_t _p = (uint32_t)(par); uint32_t _d;    \
    asm volatile("{\n\t.reg .pred p;\n\t"                                          \
        "mbarrier.try_wait.parity.acquire.cta.shared::cta.b64 p, [%1], %2;\n\t"    \
        "selp.b32 %0, 1, 0, p;\n\t}" : "=r"(_d) : "r"(_m), "r"(_p) : "memory");    \
    if (!_d) {                                                                     \
        asm volatile("{\n\t.reg .pred P1;\n\t"                                     \
            "WL_%=:\n\t"                                                           \
            "mbarrier.try_wait.parity.acquire.cta.shared::cta.b64 P1, [%0], %1, 0x989680;\n\t" \
            "@P1 bra.uni WD_%=;\n\t"                                               \
            "bra.uni WL_%=;\n\t"                                                   \
            "WD_%=:\n\t}" :: "r"(_m), "r"(_p) : "memory");                         \
    } } while (0)

__device__ __forceinline__ void cp_bulk(uint32_t smem_addr, const void* gptr,
                                        uint32_t bytes, uint32_t mbar) {
    asm volatile(
        "cp.async.bulk.shared::cluster.global.mbarrier::complete_tx::bytes [%0], [%1], %2, [%3];"
        :: "r"(smem_addr), "l"(gptr), "r"(bytes), "r"(mbar) : "memory");
}

// ---------------------------------------------------------------------------
// Preconvert: x -> fp16 (same layout), W -> fp16 gate-interleaved [h][n][k].
// ---------------------------------------------------------------------------
__global__ __launch_bounds__(256) void conv_x(const float* __restrict__ x)
{
    const size_t i = ((size_t)blockIdx.x * 256 + threadIdx.x) * 4;
    const float4 v = *(const float4*)(x + i);
    __half2 lo = __floats2half2_rn(v.x, v.y);
    __half2 hi = __floats2half2_rn(v.z, v.w);
    *(uint2*)(g_xh + i) = make_uint2(*(uint32_t*)&lo, *(uint32_t*)&hi);
}

__global__ __launch_bounds__(256) void conv_w(
    const float* __restrict__ Wz, const float* __restrict__ Wi,
    const float* __restrict__ Wf, const float* __restrict__ Wo)
{
    const size_t q = (size_t)blockIdx.x * 256 + threadIdx.x;   // float4 index
    const size_t j = q * 4;
    const int h = (int)(j >> 18);
    const int n = (int)((j >> 8) & 1023);
    const int k = (int)(j & 255);
    const int g = n & 3;
    const int o = n >> 2;
    const float* W = (g == 0) ? Wz : (g == 1) ? Wi : (g == 2) ? Wf : Wo;
    const float4 v = *(const float4*)&W[((size_t)(h * HDm + o)) * HDm + k];
    __half2 lo = __floats2half2_rn(v.x, v.y);
    __half2 hi = __floats2half2_rn(v.z, v.w);
    *(uint2*)(g_wh + j) = make_uint2(*(uint32_t*)&lo, *(uint32_t*)&hi);
}

// ---------------------------------------------------------------------------
// fp16 mma m16n8k16 + ldmatrix
// ---------------------------------------------------------------------------
__device__ __forceinline__ void mma_fp16(float c[4], const uint32_t a[4], const uint32_t b[2]) {
    asm volatile(
        "mma.sync.aligned.m16n8k16.row.col.f32.f16.f16.f32 "
        "{%0,%1,%2,%3}, {%4,%5,%6,%7}, {%8,%9}, {%0,%1,%2,%3};"
        : "+f"(c[0]), "+f"(c[1]), "+f"(c[2]), "+f"(c[3])
        : "r"(a[0]), "r"(a[1]), "r"(a[2]), "r"(a[3]), "r"(b[0]), "r"(b[1]));
}
__device__ __forceinline__ void ldsm_x4(uint32_t addr, uint32_t r[4]) {
    asm volatile("ldmatrix.sync.aligned.m8n8.x4.shared.b16 {%0,%1,%2,%3}, [%4];"
                 : "=r"(r[0]), "=r"(r[1]), "=r"(r[2]), "=r"(r[3]) : "r"(addr));
}

// ---------------------------------------------------------------------------
// Pregate GEMM — mainloop R14 verbatim (fallback-HMMA ceiling ~24 cyc/HMMA).
// Epilogue: transform z -> tanh(z) and o -> sigmoid(o) at R9's validated
// store addresses; i and f stored RAW (stabilized chain needs them).
// col%4==0 pair = (z,i); col%4==2 pair = (f,o).
// ---------------------------------------------------------------------------
#define BM 128
#define BN 128
#define BKH 32
#define NITER (HDm / BKH)       // 8
#define ROWB 80
#define STAGEB (256 * ROWB)     // 20480 B

__global__ __launch_bounds__(256, 2) void pregate_gemm(void)
{
    __shared__ __align__(16) char sm[3 * STAGEB];
    const uint32_t sbase = smem_to_u32(sm);

    const int tid  = threadIdx.x;
    const int lane = tid & 31;
    const int wid  = tid >> 5;
    const int wm   = wid & 1;
    const int wn   = wid >> 1;
    const int grp  = lane >> 2;
    const int tig  = lane & 3;

    const int n0 = blockIdx.x * BN;
    const int m0 = blockIdx.y * BM;
    const int h  = blockIdx.z;

    const int arr  = tid >> 7;
    const int row  = tid & 127;
    const __half* gsrc = arr
        ? (g_wh + ((size_t)(h * Dm + n0 + row)) * HDm)
        : (g_xh + (size_t)(m0 + row) * Dm + h * HDm);
    const uint32_t sdst = sbase + (uint32_t)tid * ROWB;

    uint32_t a_off[4], b_off[2];
    #pragma unroll
    for (int mf = 0; mf < 4; mf++)
        a_off[mf] = (uint32_t)((wm * 64 + mf * 16 + (lane & 15)) * ROWB + ((lane >> 4) * 8) * 2);
    #pragma unroll
    for (int p = 0; p < 2; p++)
        b_off[p] = (uint32_t)((128 + wn * 32 + p * 16 + ((lane >> 4) & 1) * 8 + (lane & 7)) * ROWB
                              + (((lane >> 3) & 1) * 8) * 2);

    float acc[4][4][4];
    #pragma unroll
    for (int mf = 0; mf < 4; mf++)
        #pragma unroll
        for (int nf = 0; nf < 4; nf++)
            #pragma unroll
            for (int i = 0; i < 4; i++) acc[mf][nf][i] = 0.0f;

    #pragma unroll
    for (int s = 0; s < 2; s++) {
        #pragma unroll
        for (int j = 0; j < 4; j++)
            cp_async16(sdst + s * STAGEB + j * 16, gsrc + s * BKH + j * 8);
        asm volatile("cp.async.commit_group;" ::: "memory");
    }

    #pragma unroll 1
    for (int it = 0; it < NITER; it++) {
        if (it < NITER - 1) asm volatile("cp.async.wait_group 1;" ::: "memory");
        else                asm volatile("cp.async.wait_group 0;" ::: "memory");
        __syncthreads();

        if (it + 2 < NITER) {
            const uint32_t so = (uint32_t)((it + 2) % 3) * STAGEB;
            const __half* gp = gsrc + (it + 2) * BKH;
            #pragma unroll
            for (int j = 0; j < 4; j++)
                cp_async16(sdst + so + j * 16, gp + j * 8);
            asm volatile("cp.async.commit_group;" ::: "memory");
        }

        const uint32_t stg = sbase + (uint32_t)(it % 3) * STAGEB;
        #pragma unroll
        for (int kk = 0; kk < 2; kk++) {
            const uint32_t ko = (uint32_t)(kk * 32);
            uint32_t a[4][4], b[2][4];
            #pragma unroll
            for (int mf = 0; mf < 4; mf++) ldsm_x4(stg + a_off[mf] + ko, a[mf]);
            #pragma unroll
            for (int p = 0; p < 2; p++)    ldsm_x4(stg + b_off[p] + ko, b[p]);
            #pragma unroll
            for (int mf = 0; mf < 4; mf++)
                #pragma unroll
                for (int nf = 0; nf < 4; nf++)
                    mma_fp16(acc[mf][nf], a[mf], &b[nf >> 1][(nf & 1) * 2]);
        }
    }

    // ---- epilogue: partial transform (tanh z / sig o) + R9 store addresses ----
    float* gbuf = (float*)g_gates;
    #pragma unroll
    for (int mf = 0; mf < 4; mf++) {
        const int r = m0 + wm * 64 + mf * 16 + grp;
        float* orow = gbuf + (size_t)r * 4096 + h * 1024;
        #pragma unroll
        for (int nf = 0; nf < 4; nf++) {
            const int col = n0 + wn * 32 + nf * 8 + 2 * tig;
            float2 v01, v23;
            if ((col & 2) == 0) {          // cols (4o+0, 4o+1) = (z, i): tanh z, raw i
                v01 = make_float2(mtanh(acc[mf][nf][0]), acc[mf][nf][1]);
                v23 = make_float2(mtanh(acc[mf][nf][2]), acc[mf][nf][3]);
            } else {                       // cols (4o+2, 4o+3) = (f, o): raw f, sig o
                v01 = make_float2(acc[mf][nf][0], msig(acc[mf][nf][1]));
                v23 = make_float2(acc[mf][nf][2], msig(acc[mf][nf][3]));
            }
            *(float2*)&orow[col]                    = v01;
            *(float2*)&orow[col + (size_t)8 * 4096] = v23;
        }
    }
}

// ---------------------------------------------------------------------------
// Sequential scan — R14 structure verbatim. Consumer: validated stabilized
// max-chain on RAW i/f, with tanh(z) and sigmoid(o) precomputed by the GEMM.
// Per-step MUFU: 1 chain exp + 1 off-chain rcp (R14 had 4).
// ---------------------------------------------------------------------------
#define CH    64
#define NBUF  3
#define NCH   (Sm / CH)                   // 64
#define CHBYTES (CH * 64 * 16)            // 65536
#define MB_FULL(i)  (mb_base + (i) * 8)
#define MB_EMPTY(i) (mb_base + 24 + (i) * 8)
#define SCAN_SMEM (1024 + NBUF * CHBYTES) // 197632 B

__global__ __launch_bounds__(128) void slstm_scan(float* __restrict__ out)
{
    extern __shared__ __align__(16) char smem[];
    const uint32_t mb_base = smem_to_u32(smem);
    float4* sdata = (float4*)(smem + 1024);
    const uint32_t sdata_u32 = mb_base + 1024;

    const int tid = threadIdx.x;
    const int b   = blockIdx.x >> 4;             // 8 batches x 16 d-tiles of 64
    const int d0  = (blockIdx.x & 15) * 64;
    const size_t tb = (size_t)b * Sm;

    if (tid == 0) {
        #pragma unroll
        for (int i = 0; i < NBUF; i++) {
            MBARRIER_INIT(MB_FULL(i), 1);
            MBARRIER_INIT(MB_EMPTY(i), 64);
        }
    }
    __syncthreads();

    if (tid == 64) {
        // ---- producer: 64 x 1KB bulk copies per 64-step chunk ----
        int stage = 0, ph = 1;
        #pragma unroll 1
        for (int ck = 0; ck < NCH; ck++) {
            MBARRIER_WAIT_PARITY(MB_EMPTY(stage), ph);
            MBARRIER_EXPECT_TX(MB_FULL(stage), CHBYTES);
            const float4* src = g_gates + (tb + (size_t)ck * CH) * Dm + d0;
            const uint32_t dst = sdata_u32 + (uint32_t)stage * CHBYTES;
            #pragma unroll 4
            for (int j = 0; j < CH; j++)
                cp_bulk(dst + (uint32_t)j * 1024, src + (size_t)j * Dm, 1024, MB_FULL(stage));
            if (++stage == NBUF) { stage = 0; ph ^= 1; }
        }
    } else if (tid < 64) {
        // ---- consumer: stabilized chain, 2 MUFU/step ----
        float c = 0.0f, n = 0.0f, m = 0.0f;
        float* orow = out + tb * Dm + d0 + tid;
        int stage = 0, ph = 0;
        #pragma unroll 1
        for (int ck = 0; ck < NCH; ck++) {
            MBARRIER_WAIT_PARITY(MB_FULL(stage), ph);
            const float4* buf = sdata + stage * (CHBYTES / 16);
            float* op = orow + (size_t)ck * CH * Dm;
            #pragma unroll 1
            for (int jj = 0; jj < CH; jj += 8) {
                // Phase A: batch the 8 loads (latency hiding)
                float4 g[8];
                #pragma unroll
                for (int q = 0; q < 8; q++)
                    g[q] = buf[(jj + q) * 64 + tid];
                // Phase B: serial carry chain (math = R14/R9 on i,f)
                #pragma unroll
                for (int q = 0; q < 8; q++) {
                    const float zp = g[q].x, it_ = g[q].y, ft = g[q].z, op_ = g[q].w;
                    const float fm  = ft + m;
                    const bool  fge = (fm >= it_);
                    const float e_  = mexp(-fabsf(fm - it_));
                    const float i_hat = fge ? e_ : 1.0f;
                    const float f_hat = fge ? 1.0f : e_;
                    m = fmaxf(fm, it_);

                    c = fmaf(f_hat, c, i_hat * zp);
                    n = fmaf(f_hat, n, i_hat);

                    op[(size_t)(jj + q) * Dm] = op_ * c * mrcp(n + 1e-8f);
                }
            }
            MBARRIER_ARRIVE(MB_EMPTY(stage));
            if (++stage == NBUF) { stage = 0; ph ^= 1; }
        }
    }
}

// ---------------------------------------------------------------------------
extern "C" void kernel_launch(void* const* d_in, const int* in_sizes, int n_in,
                              void* d_out, int out_size)
{
    const float* x  = (const float*)d_in[0];
    const float* Wz = (const float*)d_in[1];
    const float* Wi = (const float*)d_in[2];
    const float* Wf = (const float*)d_in[3];
    const float* Wo = (const float*)d_in[4];
    float* out = (float*)d_out;

    conv_x<<<(MTOK * Dm / 4) / 256, 256>>>(x);
    conv_w<<<(HH * Dm * HDm / 4) / 256, 256>>>(Wz, Wi, Wf, Wo);

    dim3 grid(Dm / BN, MTOK / BM, HH);   // (8, 256, 4)
    pregate_gemm<<<grid, 256>>>();

    cudaFuncSetAttribute(slstm_scan, cudaFuncAttributeMaxDynamicSharedMemorySize, SCAN_SMEM);
    slstm_scan<<<128, 128, SCAN_SMEM>>>(out);
}

// round 16
// speedup vs baseline: 1.1535x; 1.1535x over previous
#include <cuda_runtime.h>
#include <cuda_fp16.h>
#include <cstdint>

// ---------------------------------------------------------------------------
// Problem constants
// ---------------------------------------------------------------------------
#define HH   4
#define HDm  256
#define Dm   1024
#define Sm   4096
#define Bm   8
#define MTOK (Bm * Sm)   // 32768 tokens

// Gate scratch: fp32, [token][d], stored as (tanh z, i_raw, f_raw, sig o).
__device__ float4 g_gates[(size_t)MTOK * Dm];
// fp16 copies of x and gate-interleaved W for cp.async streaming.
__device__ __half g_xh[(size_t)MTOK * Dm];            // 64 MB
__device__ __half g_wh[(size_t)HH * Dm * HDm];        // 2 MB: [h][n][k], n=o*4+g

#define L2E 1.4426950408889634f

__device__ __forceinline__ uint32_t smem_to_u32(const void* p) {
    uint32_t a;
    asm("{ .reg .u64 t; cvta.to.shared.u64 t, %1; cvt.u32.u64 %0, t; }" : "=r"(a) : "l"(p));
    return a;
}
__device__ __forceinline__ void cp_async16(uint32_t smem_addr, const void* gptr) {
    asm volatile("cp.async.cg.shared.global [%0], [%1], 16;"
                 :: "r"(smem_addr), "l"(gptr) : "memory");
}
__device__ __forceinline__ float mexp(float x) {
    float r; asm("ex2.approx.f32 %0, %1;" : "=f"(r) : "f"(x * L2E)); return r;
}
__device__ __forceinline__ float mtanh(float x) {
    float r; asm("tanh.approx.f32 %0, %1;" : "=f"(r) : "f"(x)); return r;
}
__device__ __forceinline__ float mrcp(float x) {
    float r; asm("rcp.approx.f32 %0, %1;" : "=f"(r) : "f"(x)); return r;
}
__device__ __forceinline__ float msig(float x) {
    return mrcp(1.0f + mexp(-x));
}

// ---- mbarrier helpers ----
#define MBARRIER_INIT(addr, cnt) \
    asm volatile("mbarrier.init.shared.b64 [%0], %1;" :: "r"((uint32_t)(addr)), "r"((uint32_t)(cnt)) : "memory")
#define MBARRIER_EXPECT_TX(addr, bytes) \
    asm volatile("mbarrier.arrive.expect_tx.shared.b64 _, [%0], %1;" :: "r"((uint32_t)(addr)), "r"((uint32_t)(bytes)) : "memory")
#define MBARRIER_ARRIVE(addr) \
    asm volatile("mbarrier.arrive.shared.b64 _, [%0];" :: "r"((uint32_t)(addr)) : "memory")
#define MBARRIER_WAIT_PARITY(addr, par) do {                                       \
    uint32_t _m = (uint32_t)(addr); uint32_t _p = (uint32_t)(par); uint32_t _d;    \
    asm volatile("{\n\t.reg .pred p;\n\t"                                          \
        "mbarrier.try_wait.parity.acquire.cta.shared::cta.b64 p, [%1], %2;\n\t"    \
        "selp.b32 %0, 1, 0, p;\n\t}" : "=r"(_d) : "r"(_m), "r"(_p) : "memory");    \
    if (!_d) {                                                                     \
        asm volatile("{\n\t.reg .pred P1;\n\t"                                     \
            "WL_%=:\n\t"                                                           \
            "mbarrier.try_wait.parity.acquire.cta.shared::cta.b64 P1, [%0], %1, 0x989680;\n\t" \
            "@P1 bra.uni WD_%=;\n\t"                                               \
            "bra.uni WL_%=;\n\t"                                                   \
            "WD_%=:\n\t}" :: "r"(_m), "r"(_p) : "memory");                         \
    } } while (0)

__device__ __forceinline__ void cp_bulk(uint32_t smem_addr, const void* gptr,
                                        uint32_t bytes, uint32_t mbar) {
    asm volatile(
        "cp.async.bulk.shared::cluster.global.mbarrier::complete_tx::bytes [%0], [%1], %2, [%3];"
        :: "r"(smem_addr), "l"(gptr), "r"(bytes), "r"(mbar) : "memory");
}

// Volatile v4 shared load — ptxas cannot sink/split it past later code.
__device__ __forceinline__ float4 lds128v(uint32_t addr) {
    float4 v;
    asm volatile("ld.volatile.shared.v4.f32 {%0,%1,%2,%3}, [%4];"
                 : "=f"(v.x), "=f"(v.y), "=f"(v.z), "=f"(v.w) : "r"(addr));
    return v;
}

// ---------------------------------------------------------------------------
// Preconvert: x -> fp16 (same layout), W -> fp16 gate-interleaved [h][n][k].
// ---------------------------------------------------------------------------
__global__ __launch_bounds__(256) void conv_x(const float* __restrict__ x)
{
    const size_t i = ((size_t)blockIdx.x * 256 + threadIdx.x) * 4;
    const float4 v = *(const float4*)(x + i);
    __half2 lo = __floats2half2_rn(v.x, v.y);
    __half2 hi = __floats2half2_rn(v.z, v.w);
    *(uint2*)(g_xh + i) = make_uint2(*(uint32_t*)&lo, *(uint32_t*)&hi);
}

__global__ __launch_bounds__(256) void conv_w(
    const float* __restrict__ Wz, const float* __restrict__ Wi,
    const float* __restrict__ Wf, const float* __restrict__ Wo)
{
    const size_t q = (size_t)blockIdx.x * 256 + threadIdx.x;   // float4 index
    const size_t j = q * 4;
    const int h = (int)(j >> 18);
    const int n = (int)((j >> 8) & 1023);
    const int k = (int)(j & 255);
    const int g = n & 3;
    const int o = n >> 2;
    const float* W = (g == 0) ? Wz : (g == 1) ? Wi : (g == 2) ? Wf : Wo;
    const float4 v = *(const float4*)&W[((size_t)(h * HDm + o)) * HDm + k];
    __half2 lo = __floats2half2_rn(v.x, v.y);
    __half2 hi = __floats2half2_rn(v.z, v.w);
    *(uint2*)(g_wh + j) = make_uint2(*(uint32_t*)&lo, *(uint32_t*)&hi);
}

// ---------------------------------------------------------------------------
// fp16 mma m16n8k16 + ldmatrix
// ---------------------------------------------------------------------------
__device__ __forceinline__ void mma_fp16(float c[4], const uint32_t a[4], const uint32_t b[2]) {
    asm volatile(
        "mma.sync.aligned.m16n8k16.row.col.f32.f16.f16.f32 "
        "{%0,%1,%2,%3}, {%4,%5,%6,%7}, {%8,%9}, {%0,%1,%2,%3};"
        : "+f"(c[0]), "+f"(c[1]), "+f"(c[2]), "+f"(c[3])
        : "r"(a[0]), "r"(a[1]), "r"(a[2]), "r"(a[3]), "r"(b[0]), "r"(b[1]));
}
__device__ __forceinline__ void ldsm_x4(uint32_t addr, uint32_t r[4]) {
    asm volatile("ldmatrix.sync.aligned.m8n8.x4.shared.b16 {%0,%1,%2,%3}, [%4];"
                 : "=r"(r[0]), "=r"(r[1]), "=r"(r[2]), "=r"(r[3]) : "r"(addr));
}

// ---------------------------------------------------------------------------
// Pregate GEMM — mainloop at the fallback-HMMA ceiling (~24 cyc/HMMA).
// Epilogue: tanh(z) / sigmoid(o) transforms at R9-validated store addresses;
// i, f stored RAW for the stabilized chain. (Validated: R15 passed 8.293e-4.)
// ---------------------------------------------------------------------------
#define BM 128
#define BN 128
#define BKH 32
#define NITER (HDm / BKH)       // 8
#define ROWB 80
#define STAGEB (256 * ROWB)     // 20480 B

__global__ __launch_bounds__(256, 2) void pregate_gemm(void)
{
    __shared__ __align__(16) char sm[3 * STAGEB];
    const uint32_t sbase = smem_to_u32(sm);

    const int tid  = threadIdx.x;
    const int lane = tid & 31;
    const int wid  = tid >> 5;
    const int wm   = wid & 1;
    const int wn   = wid >> 1;
    const int grp  = lane >> 2;
    const int tig  = lane & 3;

    const int n0 = blockIdx.x * BN;
    const int m0 = blockIdx.y * BM;
    const int h  = blockIdx.z;

    const int arr  = tid >> 7;
    const int row  = tid & 127;
    const __half* gsrc = arr
        ? (g_wh + ((size_t)(h * Dm + n0 + row)) * HDm)
        : (g_xh + (size_t)(m0 + row) * Dm + h * HDm);
    const uint32_t sdst = sbase + (uint32_t)tid * ROWB;

    uint32_t a_off[4], b_off[2];
    #pragma unroll
    for (int mf = 0; mf < 4; mf++)
        a_off[mf] = (uint32_t)((wm * 64 + mf * 16 + (lane & 15)) * ROWB + ((lane >> 4) * 8) * 2);
    #pragma unroll
    for (int p = 0; p < 2; p++)
        b_off[p] = (uint32_t)((128 + wn * 32 + p * 16 + ((lane >> 4) & 1) * 8 + (lane & 7)) * ROWB
                              + (((lane >> 3) & 1) * 8) * 2);

    float acc[4][4][4];
    #pragma unroll
    for (int mf = 0; mf < 4; mf++)
        #pragma unroll
        for (int nf = 0; nf < 4; nf++)
            #pragma unroll
            for (int i = 0; i < 4; i++) acc[mf][nf][i] = 0.0f;

    #pragma unroll
    for (int s = 0; s < 2; s++) {
        #pragma unroll
        for (int j = 0; j < 4; j++)
            cp_async16(sdst + s * STAGEB + j * 16, gsrc + s * BKH + j * 8);
        asm volatile("cp.async.commit_group;" ::: "memory");
    }

    #pragma unroll 1
    for (int it = 0; it < NITER; it++) {
        if (it < NITER - 1) asm volatile("cp.async.wait_group 1;" ::: "memory");
        else                asm volatile("cp.async.wait_group 0;" ::: "memory");
        __syncthreads();

        if (it + 2 < NITER) {
            const uint32_t so = (uint32_t)((it + 2) % 3) * STAGEB;
            const __half* gp = gsrc + (it + 2) * BKH;
            #pragma unroll
            for (int j = 0; j < 4; j++)
                cp_async16(sdst + so + j * 16, gp + j * 8);
            asm volatile("cp.async.commit_group;" ::: "memory");
        }

        const uint32_t stg = sbase + (uint32_t)(it % 3) * STAGEB;
        #pragma unroll
        for (int kk = 0; kk < 2; kk++) {
            const uint32_t ko = (uint32_t)(kk * 32);
            uint32_t a[4][4], b[2][4];
            #pragma unroll
            for (int mf = 0; mf < 4; mf++) ldsm_x4(stg + a_off[mf] + ko, a[mf]);
            #pragma unroll
            for (int p = 0; p < 2; p++)    ldsm_x4(stg + b_off[p] + ko, b[p]);
            #pragma unroll
            for (int mf = 0; mf < 4; mf++)
                #pragma unroll
                for (int nf = 0; nf < 4; nf++)
                    mma_fp16(acc[mf][nf], a[mf], &b[nf >> 1][(nf & 1) * 2]);
        }
    }

    // ---- epilogue: partial transform (tanh z / sig o) + R9 store addresses ----
    float* gbuf = (float*)g_gates;
    #pragma unroll
    for (int mf = 0; mf < 4; mf++) {
        const int r = m0 + wm * 64 + mf * 16 + grp;
        float* orow = gbuf + (size_t)r * 4096 + h * 1024;
        #pragma unroll
        for (int nf = 0; nf < 4; nf++) {
            const int col = n0 + wn * 32 + nf * 8 + 2 * tig;
            float2 v01, v23;
            if ((col & 2) == 0) {          // cols (4o+0, 4o+1) = (z, i): tanh z, raw i
                v01 = make_float2(mtanh(acc[mf][nf][0]), acc[mf][nf][1]);
                v23 = make_float2(mtanh(acc[mf][nf][2]), acc[mf][nf][3]);
            } else {                       // cols (4o+2, 4o+3) = (f, o): raw f, sig o
                v01 = make_float2(acc[mf][nf][0], msig(acc[mf][nf][1]));
                v23 = make_float2(acc[mf][nf][2], msig(acc[mf][nf][3]));
            }
            *(float2*)&orow[col]                    = v01;
            *(float2*)&orow[col + (size_t)8 * 4096] = v23;
        }
    }
}

// ---------------------------------------------------------------------------
// Sequential scan — R14 structure. Consumer: Phase A loads forced up-front
// with ld.volatile.shared.v4 (R15's regression: with plain loads and no
// Phase-A consumers, ptxas sank each load into the carry chain, exposing the
// 29-cyc LDS latency per step). Phase B: stabilized chain on raw i/f with
// tanh(z)/sig(o) precomputed -> 1 chain MUFU + 1 off-chain RCP per step.
// ---------------------------------------------------------------------------
#define CH    64
#define NBUF  3
#define NCH   (Sm / CH)                   // 64
#define CHBYTES (CH * 64 * 16)            // 65536
#define MB_FULL(i)  (mb_base + (i) * 8)
#define MB_EMPTY(i) (mb_base + 24 + (i) * 8)
#define SCAN_SMEM (1024 + NBUF * CHBYTES) // 197632 B

__global__ __launch_bounds__(128) void slstm_scan(float* __restrict__ out)
{
    extern __shared__ __align__(16) char smem[];
    const uint32_t mb_base = smem_to_u32(smem);
    const uint32_t sdata_u32 = mb_base + 1024;

    const int tid = threadIdx.x;
    const int b   = blockIdx.x >> 4;             // 8 batches x 16 d-tiles of 64
    const int d0  = (blockIdx.x & 15) * 64;
    const size_t tb = (size_t)b * Sm;

    if (tid == 0) {
        #pragma unroll
        for (int i = 0; i < NBUF; i++) {
            MBARRIER_INIT(MB_FULL(i), 1);
            MBARRIER_INIT(MB_EMPTY(i), 64);
        }
    }
    __syncthreads();

    if (tid == 64) {
        // ---- producer: 64 x 1KB bulk copies per 64-step chunk ----
        int stage = 0, ph = 1;
        #pragma unroll 1
        for (int ck = 0; ck < NCH; ck++) {
            MBARRIER_WAIT_PARITY(MB_EMPTY(stage), ph);
            MBARRIER_EXPECT_TX(MB_FULL(stage), CHBYTES);
            const float4* src = g_gates + (tb + (size_t)ck * CH) * Dm + d0;
            const uint32_t dst = sdata_u32 + (uint32_t)stage * CHBYTES;
            #pragma unroll 4
            for (int j = 0; j < CH; j++)
                cp_bulk(dst + (uint32_t)j * 1024, src + (size_t)j * Dm, 1024, MB_FULL(stage));
            if (++stage == NBUF) { stage = 0; ph ^= 1; }
        }
    } else if (tid < 64) {
        // ---- consumer: stabilized chain, 2 MUFU/step, pinned batch loads ----
        float c = 0.0f, n = 0.0f, m = 0.0f;
        float* orow = out + tb * Dm + d0 + tid;
        const uint32_t lbase = sdata_u32 + (uint32_t)tid * 16;
        int stage = 0, ph = 0;
        #pragma unroll 1
        for (int ck = 0; ck < NCH; ck++) {
            MBARRIER_WAIT_PARITY(MB_FULL(stage), ph);
            const uint32_t sb = lbase + (uint32_t)stage * CHBYTES;
            float* op = orow + (size_t)ck * CH * Dm;
            #pragma unroll 1
            for (int jj = 0; jj < CH; jj += 8) {
                // Phase A: 8 pinned v4 loads (volatile -> cannot be sunk)
                float4 g[8];
                const uint32_t a0 = sb + (uint32_t)jj * 1024;
                #pragma unroll
                for (int q = 0; q < 8; q++)
                    g[q] = lds128v(a0 + (uint32_t)q * 1024);
                // Phase B: serial carry chain (math = R14/R15)
                #pragma unroll
                for (int q = 0; q < 8; q++) {
                    const float zp = g[q].x, it_ = g[q].y, ft = g[q].z, op_ = g[q].w;
                    const float fm  = ft + m;
                    const bool  fge = (fm >= it_);
                    const float e_  = mexp(-fabsf(fm - it_));
                    const float i_hat = fge ? e_ : 1.0f;
                    const float f_hat = fge ? 1.0f : e_;
                    m = fmaxf(fm, it_);

                    c = fmaf(f_hat, c, i_hat * zp);
                    n = fmaf(f_hat, n, i_hat);

                    op[(size_t)(jj + q) * Dm] = op_ * c * mrcp(n + 1e-8f);
                }
            }
            MBARRIER_ARRIVE(MB_EMPTY(stage));
            if (++stage == NBUF) { stage = 0; ph ^= 1; }
        }
    }
}

// ---------------------------------------------------------------------------
extern "C" void kernel_launch(void* const* d_in, const int* in_sizes, int n_in,
                              void* d_out, int out_size)
{
    const float* x  = (const float*)d_in[0];
    const float* Wz = (const float*)d_in[1];
    const float* Wi = (const float*)d_in[2];
    const float* Wf = (const float*)d_in[3];
    const float* Wo = (const float*)d_in[4];
    float* out = (float*)d_out;

    conv_x<<<(MTOK * Dm / 4) / 256, 256>>>(x);
    conv_w<<<(HH * Dm * HDm / 4) / 256, 256>>>(Wz, Wi, Wf, Wo);

    dim3 grid(Dm / BN, MTOK / BM, HH);   // (8, 256, 4)
    pregate_gemm<<<grid, 256>>>();

    cudaFuncSetAttribute(slstm_scan, cudaFuncAttributeMaxDynamicSharedMemorySize, SCAN_SMEM);
    slstm_scan<<<128, 128, SCAN_SMEM>>>(out);
}